// round 10
// baseline (speedup 1.0000x reference)
#include <cuda_runtime.h>

// SparseBiasDiagUnfolder: gather off-diagonal 8x8 window entries.
// adj: (B=2, N=2048, N=2048, F=16) f32
// out: (B=2, S=511, 56*16=896) f32
// out[b, s, k*16+f] = adj[b, 4*s + ii(k), 4*s + jj(k), f]
// local = k + 1 + k/8 (skips diagonal multiples of 9), ii = local/8, jj = local%8.
//
// TOT4 = 2*511*56*4 = 228928 = 32 * 14 * 511 float4 outputs.
// Max-MLP probe: TPB=32 (1 warp), U=14 -> 511 blocks, zero predication.
// 14 front-batched independent LDG.128s per thread (7 KB in flight per warp,
// ~7.3 MB chip-wide = the entire read band), stride-TPB coalesced stores.

namespace {
constexpr int B  = 2;
constexpr int N  = 2048;
constexpr int S  = 511;
constexpr int K  = 56;
constexpr int TOT4 = B * S * K * 4;      // 228928
constexpr int U  = 14;
constexpr int TPB = 32;
constexpr int BLOCKS = TOT4 / (TPB * U); // 511
static_assert(BLOCKS * TPB * U == TOT4, "exact tiling");
}

__device__ __forceinline__ int src_index(int t) {
    int f4   = t & 3;            // float4 within the 16-float feature vec
    int t2   = t >> 2;           // (b, s, k)
    int k    = t2 % K;
    int rest = t2 / K;
    int s    = rest % S;
    int b    = rest / S;

    int local = k + 1 + (k >> 3);    // skip diagonal
    int r = (s << 2) + (local >> 3);
    int c = (s << 2) + (local & 7);
    return (((b * N) + r) * N + c) * 4 + f4;
}

__global__ void __launch_bounds__(TPB)
sparse_diag_unfold_kernel(const float4* __restrict__ adj4,
                          float4* __restrict__ out4) {
    const int base = blockIdx.x * (TPB * U) + threadIdx.x;

    // Front-batched independent loads (no guards, no inter-load deps):
    // ptxas emits 14 back-to-back LDG.128s.
    float4 v[U];
    #pragma unroll
    for (int u = 0; u < U; u++) {
        v[u] = __ldg(&adj4[src_index(base + u * TPB)]);
    }

    // Fully coalesced stores.
    #pragma unroll
    for (int u = 0; u < U; u++) {
        out4[base + u * TPB] = v[u];
    }
}

extern "C" void kernel_launch(void* const* d_in, const int* in_sizes, int n_in,
                              void* d_out, int out_size) {
    const float4* adj4 = (const float4*)d_in[0];
    float4* out4 = (float4*)d_out;
    sparse_diag_unfold_kernel<<<BLOCKS, TPB>>>(adj4, out4);
}